// round 1
// baseline (speedup 1.0000x reference)
#include <cuda_runtime.h>
#include <math.h>

#define BATCH 2
#define SEQ 2048
#define EMB 1024
#define NH 16
#define HD 64
#define MROWS (BATCH * SEQ)   // 4096

// ---------------- scratch (static device allocation, allowed) ----------------
__device__ float g_q[BATCH * NH * SEQ * HD];   // [b][h][s][d]
__device__ float g_k[BATCH * NH * SEQ * HD];
__device__ float g_v[BATCH * NH * SEQ * HD];
__device__ float g_ctx[MROWS * EMB];           // [b*s][e]

// ============================================================================
// GEMM: C[4096, 1024] = A @ W  (A row-major [M,K], W row-major [K,N])
// 128x128x16 tiles, 256 threads, 8x8 per thread, register prefetch.
// mode 0/1/2: epilogue scatters into g_q/g_k/g_v split-head layout.
// mode 3:     A := g_ctx, epilogue adds bias, writes to outp.
// ============================================================================
#define GBM 128
#define GBN 128
#define GBK 16

__global__ __launch_bounds__(256, 2) void gemm_kernel(
    const float* __restrict__ A,
    const float* __restrict__ w0, const float* __restrict__ w1,
    const float* __restrict__ w2,
    const float* __restrict__ bias, float* __restrict__ outp, int mode_base)
{
    __shared__ float As[GBK][GBM];   // transposed: As[k][m]
    __shared__ float Bs[GBK][GBN];   // Bs[k][n]

    const int mode = mode_base + blockIdx.z;
    const float* W  = (mode == 1) ? w1 : (mode == 2) ? w2 : w0;
    const float* Ap = (mode == 3) ? g_ctx : A;

    const int m0 = blockIdx.y * GBM;
    const int n0 = blockIdx.x * GBN;
    const int tid = threadIdx.x;
    const int tx = tid & 15;        // 0..15 -> cols tx*8..tx*8+7
    const int ty = tid >> 4;        // 0..15 -> rows ty*8..ty*8+7

    float acc[8][8];
    #pragma unroll
    for (int i = 0; i < 8; i++)
        #pragma unroll
        for (int j = 0; j < 8; j++) acc[i][j] = 0.f;

    // staging indices
    const int arow = tid >> 2;          // 0..63
    const int acol = (tid & 3) * 4;     // 0,4,8,12
    const int brow = tid >> 5;          // 0..7
    const int bcol = (tid & 31) * 4;    // 0..124

    const int NT = EMB / GBK;           // 64 k-tiles

    // ---- load k-tile 0 into smem ----
    {
        float4 a0 = *(const float4*)(Ap + (size_t)(m0 + arow) * EMB + acol);
        float4 a1 = *(const float4*)(Ap + (size_t)(m0 + arow + 64) * EMB + acol);
        float4 b0 = *(const float4*)(W + (size_t)(brow) * EMB + n0 + bcol);
        float4 b1 = *(const float4*)(W + (size_t)(brow + 8) * EMB + n0 + bcol);
        As[acol + 0][arow] = a0.x; As[acol + 1][arow] = a0.y;
        As[acol + 2][arow] = a0.z; As[acol + 3][arow] = a0.w;
        As[acol + 0][arow + 64] = a1.x; As[acol + 1][arow + 64] = a1.y;
        As[acol + 2][arow + 64] = a1.z; As[acol + 3][arow + 64] = a1.w;
        *(float4*)&Bs[brow][bcol]     = b0;
        *(float4*)&Bs[brow + 8][bcol] = b1;
    }
    __syncthreads();

    for (int kt = 0; kt < NT; kt++) {
        // prefetch next tile to registers (overlaps with compute)
        float4 na0 = make_float4(0,0,0,0), na1 = na0, nb0 = na0, nb1 = na0;
        if (kt + 1 < NT) {
            const int k0 = (kt + 1) * GBK;
            na0 = *(const float4*)(Ap + (size_t)(m0 + arow) * EMB + k0 + acol);
            na1 = *(const float4*)(Ap + (size_t)(m0 + arow + 64) * EMB + k0 + acol);
            nb0 = *(const float4*)(W + (size_t)(k0 + brow) * EMB + n0 + bcol);
            nb1 = *(const float4*)(W + (size_t)(k0 + brow + 8) * EMB + n0 + bcol);
        }

        #pragma unroll
        for (int kk = 0; kk < GBK; kk++) {
            float a[8], b[8];
            #pragma unroll
            for (int i = 0; i < 8; i++) a[i] = As[kk][ty * 8 + i];
            #pragma unroll
            for (int j = 0; j < 8; j++) b[j] = Bs[kk][tx * 8 + j];
            #pragma unroll
            for (int i = 0; i < 8; i++)
                #pragma unroll
                for (int j = 0; j < 8; j++)
                    acc[i][j] = fmaf(a[i], b[j], acc[i][j]);
        }
        __syncthreads();
        if (kt + 1 < NT) {
            As[acol + 0][arow] = na0.x; As[acol + 1][arow] = na0.y;
            As[acol + 2][arow] = na0.z; As[acol + 3][arow] = na0.w;
            As[acol + 0][arow + 64] = na1.x; As[acol + 1][arow + 64] = na1.y;
            As[acol + 2][arow + 64] = na1.z; As[acol + 3][arow + 64] = na1.w;
            *(float4*)&Bs[brow][bcol]     = nb0;
            *(float4*)&Bs[brow + 8][bcol] = nb1;
        }
        __syncthreads();
    }

    // ---- epilogue ----
    if (mode < 3) {
        float* dst = (mode == 0) ? g_q : (mode == 1) ? g_k : g_v;
        const int n = n0 + tx * 8;        // 8 contiguous cols, within one head
        const int h = n >> 6, d = n & 63;
        #pragma unroll
        for (int i = 0; i < 8; i++) {
            const int m = m0 + ty * 8 + i;
            const int bb = m >> 11, ss = m & 2047;
            float* p = &dst[((size_t)((bb * NH + h) * SEQ) + ss) * HD + d];
            *(float4*)(p)     = make_float4(acc[i][0], acc[i][1], acc[i][2], acc[i][3]);
            *(float4*)(p + 4) = make_float4(acc[i][4], acc[i][5], acc[i][6], acc[i][7]);
        }
    } else {
        const int n = n0 + tx * 8;
        float4 bv0 = *(const float4*)(bias + n);
        float4 bv1 = *(const float4*)(bias + n + 4);
        #pragma unroll
        for (int i = 0; i < 8; i++) {
            const int m = m0 + ty * 8 + i;
            float* p = outp + (size_t)m * EMB + n;
            *(float4*)(p) = make_float4(acc[i][0] + bv0.x, acc[i][1] + bv0.y,
                                        acc[i][2] + bv0.z, acc[i][3] + bv0.w);
            *(float4*)(p + 4) = make_float4(acc[i][4] + bv1.x, acc[i][5] + bv1.y,
                                            acc[i][6] + bv1.z, acc[i][7] + bv1.w);
        }
    }
}

// ============================================================================
// Causal flash attention, fp32. One block per (q-tile, head, batch).
// 64x64 tiles, 128 threads (ty=tid/8 owns 4 rows; tx=tid%8 owns strided cols
// c = tx + 8*j  -> conflict-free Ks/Vs LDS since stride 68 is ~odd in banks).
// ============================================================================
#define FS 64
#define FSTR 68   // padded row stride in smem (floats)
#define FLASH_SMEM (4 * FS * FSTR * (int)sizeof(float))  // Qs,Ks,Vs,Ps = 69632 B

__global__ __launch_bounds__(128) void flash_kernel()
{
    extern __shared__ float sm[];
    float* Qs = sm;
    float* Ks = Qs + FS * FSTR;
    float* Vs = Ks + FS * FSTR;
    float* Ps = Vs + FS * FSTR;

    const int qt = blockIdx.x;
    const int h  = blockIdx.y;
    const int b  = blockIdx.z;
    const int q0 = qt * FS;

    const float* Qg = g_q + (size_t)((b * NH + h) * SEQ) * HD;
    const float* Kg = g_k + (size_t)((b * NH + h) * SEQ) * HD;
    const float* Vg = g_v + (size_t)((b * NH + h) * SEQ) * HD;

    const int tid = threadIdx.x;
    const int tx = tid & 7;     // col group
    const int ty = tid >> 3;    // row group (0..15), rows ty*4..ty*4+3

    // load Q tile (64x64)
    {
        const int row = tid >> 4;           // 0..7
        const int c4  = (tid & 15) * 4;     // 0..60
        #pragma unroll
        for (int p = 0; p < 8; p++) {
            *(float4*)&Qs[(row + p * 8) * FSTR + c4] =
                *(const float4*)(Qg + (size_t)(q0 + row + p * 8) * HD + c4);
        }
    }

    float mrow[4], lrow[4], o[4][8];
    #pragma unroll
    for (int i = 0; i < 4; i++) {
        mrow[i] = -3.0e38f; lrow[i] = 0.f;
        #pragma unroll
        for (int c = 0; c < 8; c++) o[i][c] = 0.f;
    }

    const int ntiles = qt + 1;
    for (int jt = 0; jt < ntiles; jt++) {
        const int j0 = jt * FS;
        // load K,V tiles
        {
            const int row = tid >> 4;
            const int c4  = (tid & 15) * 4;
            #pragma unroll
            for (int p = 0; p < 8; p++) {
                *(float4*)&Ks[(row + p * 8) * FSTR + c4] =
                    *(const float4*)(Kg + (size_t)(j0 + row + p * 8) * HD + c4);
                *(float4*)&Vs[(row + p * 8) * FSTR + c4] =
                    *(const float4*)(Vg + (size_t)(j0 + row + p * 8) * HD + c4);
            }
        }
        __syncthreads();

        // S = Q K^T  (4x8 per thread)
        float s[4][8];
        #pragma unroll
        for (int i = 0; i < 4; i++)
            #pragma unroll
            for (int j = 0; j < 8; j++) s[i][j] = 0.f;

        #pragma unroll 4
        for (int d = 0; d < HD; d++) {
            float qv[4], kv[8];
            #pragma unroll
            for (int i = 0; i < 4; i++) qv[i] = Qs[(ty * 4 + i) * FSTR + d];
            #pragma unroll
            for (int j = 0; j < 8; j++) kv[j] = Ks[(tx + 8 * j) * FSTR + d];
            #pragma unroll
            for (int i = 0; i < 4; i++)
                #pragma unroll
                for (int j = 0; j < 8; j++)
                    s[i][j] = fmaf(qv[i], kv[j], s[i][j]);
        }

        // scale + causal mask (only diagonal tile can mask)
        const float scale = 0.125f;   // 1/sqrt(64)
        const bool diag = (jt == qt);
        #pragma unroll
        for (int i = 0; i < 4; i++)
            #pragma unroll
            for (int j = 0; j < 8; j++) {
                float v = s[i][j] * scale;
                if (diag && (j0 + tx + 8 * j) > (q0 + ty * 4 + i)) v = -3.0e38f;
                s[i][j] = v;
            }

        // online softmax per row (8 lanes share a row; reduce via bfly)
        #pragma unroll
        for (int i = 0; i < 4; i++) {
            float mx = s[i][0];
            #pragma unroll
            for (int j = 1; j < 8; j++) mx = fmaxf(mx, s[i][j]);
            mx = fmaxf(mx, __shfl_xor_sync(0xffffffffu, mx, 1));
            mx = fmaxf(mx, __shfl_xor_sync(0xffffffffu, mx, 2));
            mx = fmaxf(mx, __shfl_xor_sync(0xffffffffu, mx, 4));
            const float mnew = fmaxf(mrow[i], mx);
            const float alpha = __expf(mrow[i] - mnew);
            const int r = ty * 4 + i;
            float rs = 0.f;
            #pragma unroll
            for (int j = 0; j < 8; j++) {
                const float p = __expf(s[i][j] - mnew);
                Ps[r * FSTR + tx + 8 * j] = p;
                rs += p;
            }
            rs += __shfl_xor_sync(0xffffffffu, rs, 1);
            rs += __shfl_xor_sync(0xffffffffu, rs, 2);
            rs += __shfl_xor_sync(0xffffffffu, rs, 4);
            lrow[i] = lrow[i] * alpha + rs;
            mrow[i] = mnew;
            #pragma unroll
            for (int c = 0; c < 8; c++) o[i][c] *= alpha;
        }
        __syncwarp();   // P rows are produced & consumed within one warp

        // O += P V
        #pragma unroll 4
        for (int jj = 0; jj < FS; jj++) {
            float pv[4], vv[8];
            #pragma unroll
            for (int i = 0; i < 4; i++) pv[i] = Ps[(ty * 4 + i) * FSTR + jj];
            #pragma unroll
            for (int c = 0; c < 8; c++) vv[c] = Vs[jj * FSTR + tx + 8 * c];
            #pragma unroll
            for (int i = 0; i < 4; i++)
                #pragma unroll
                for (int c = 0; c < 8; c++)
                    o[i][c] = fmaf(pv[i], vv[c], o[i][c]);
        }
        __syncthreads();   // before next tile overwrites Ks/Vs
    }

    // epilogue: ctx[b][q][h*64 + c]
    #pragma unroll
    for (int i = 0; i < 4; i++) {
        const int r = q0 + ty * 4 + i;
        const float inv = 1.f / lrow[i];
        #pragma unroll
        for (int c = 0; c < 8; c++) {
            g_ctx[(size_t)(b * SEQ + r) * EMB + h * HD + tx + 8 * c] = o[i][c] * inv;
        }
    }
}

// ============================================================================
// launch
// ============================================================================
extern "C" void kernel_launch(void* const* d_in, const int* in_sizes, int n_in,
                              void* d_out, int out_size)
{
    (void)in_sizes; (void)n_in; (void)out_size;
    const float* x  = (const float*)d_in[0];
    const float* wq = (const float*)d_in[1];
    const float* wk = (const float*)d_in[2];
    const float* wv = (const float*)d_in[3];
    const float* wo = (const float*)d_in[4];
    const float* bo = (const float*)d_in[5];
    float* out = (float*)d_out;

    cudaFuncSetAttribute(flash_kernel,
                         cudaFuncAttributeMaxDynamicSharedMemorySize, FLASH_SMEM);

    // 1) QKV projections with split-head scatter
    dim3 gq(EMB / GBN, MROWS / GBM, 3);   // 8, 32, 3
    gemm_kernel<<<gq, 256>>>(x, wq, wk, wv, nullptr, nullptr, 0);

    // 2) causal flash attention
    dim3 fg(SEQ / FS, NH, BATCH);          // 32, 16, 2
    flash_kernel<<<fg, 128, FLASH_SMEM>>>();

    // 3) output projection + bias (reads g_ctx internally)
    dim3 go(EMB / GBN, MROWS / GBM, 1);
    gemm_kernel<<<go, 256>>>(nullptr, wo, nullptr, nullptr, bo, out, 3);
}

// round 3
// speedup vs baseline: 1.4568x; 1.4568x over previous
#include <cuda_runtime.h>
#include <cuda_bf16.h>
#include <math.h>
#include <stdint.h>

#define BATCH 2
#define SEQ 2048
#define EMB 1024
#define NH 16
#define HD 64
#define MROWS (BATCH * SEQ)   // 4096

// ---------------- scratch (static device allocation, allowed) ----------------
__device__ float g_q[BATCH * NH * SEQ * HD];   // [b][h][s][d] fp32
__device__ float g_k[BATCH * NH * SEQ * HD];
__device__ float g_v[BATCH * NH * SEQ * HD];

// bf16 hi/lo split operands for tensor-core GEMMs
__device__ __nv_bfloat16 g_xhi[MROWS * EMB];
__device__ __nv_bfloat16 g_xlo[MROWS * EMB];
__device__ __nv_bfloat16 g_chi[MROWS * EMB];   // ctx (written by flash epilogue)
__device__ __nv_bfloat16 g_clo[MROWS * EMB];
__device__ __nv_bfloat16 g_wthi[4 * EMB * EMB];  // W^T [n][k], order q,k,v,o
__device__ __nv_bfloat16 g_wtlo[4 * EMB * EMB];

// ============================================================================
// helpers
// ============================================================================
__device__ __forceinline__ uint32_t smem_u32(const void* p) {
    uint32_t a;
    asm("{ .reg .u64 t; cvta.to.shared.u64 t, %1; cvt.u32.u64 %0, t; }" : "=r"(a) : "l"(p));
    return a;
}
__device__ __forceinline__ void cpa16(uint32_t dst, const void* src) {
    asm volatile("cp.async.cg.shared.global [%0], [%1], 16;" :: "r"(dst), "l"(src));
}
#define CPA_COMMIT() asm volatile("cp.async.commit_group;" ::: "memory")

#define LDSM4(r0, r1, r2, r3, a) \
    asm volatile("ldmatrix.sync.aligned.m8n8.x4.shared.b16 {%0,%1,%2,%3}, [%4];" \
        : "=r"(r0), "=r"(r1), "=r"(r2), "=r"(r3) : "r"(a))

#define MMA16816(c, a0, a1, a2, a3, b0, b1) \
    asm volatile("mma.sync.aligned.m16n8k16.row.col.f32.bf16.bf16.f32 " \
        "{%0,%1,%2,%3}, {%4,%5,%6,%7}, {%8,%9}, {%0,%1,%2,%3};" \
        : "+f"((c)[0]), "+f"((c)[1]), "+f"((c)[2]), "+f"((c)[3]) \
        : "r"(a0), "r"(a1), "r"(a2), "r"(a3), "r"(b0), "r"(b1))

// ============================================================================
// conversion kernels
// ============================================================================
__global__ void conv_x_kernel(const float* __restrict__ x) {
    int i = (blockIdx.x * 256 + threadIdx.x) * 4;
    float4 v = *(const float4*)(x + i);
    __nv_bfloat16 h0 = __float2bfloat16(v.x), h1 = __float2bfloat16(v.y);
    __nv_bfloat16 h2 = __float2bfloat16(v.z), h3 = __float2bfloat16(v.w);
    __nv_bfloat162 hi0, hi1, lo0, lo1;
    hi0.x = h0; hi0.y = h1; hi1.x = h2; hi1.y = h3;
    lo0.x = __float2bfloat16(v.x - __bfloat162float(h0));
    lo0.y = __float2bfloat16(v.y - __bfloat162float(h1));
    lo1.x = __float2bfloat16(v.z - __bfloat162float(h2));
    lo1.y = __float2bfloat16(v.w - __bfloat162float(h3));
    *(__nv_bfloat162*)(g_xhi + i)     = hi0;
    *(__nv_bfloat162*)(g_xhi + i + 2) = hi1;
    *(__nv_bfloat162*)(g_xlo + i)     = lo0;
    *(__nv_bfloat162*)(g_xlo + i + 2) = lo1;
}

// transpose + split W[k][n] -> Wt[n][k] (hi, lo)
__global__ void conv_w_kernel(const float* __restrict__ w0, const float* __restrict__ w1,
                              const float* __restrict__ w2, const float* __restrict__ w3) {
    __shared__ float t[32][33];
    const int z = blockIdx.z;
    const float* W = (z == 0) ? w0 : (z == 1) ? w1 : (z == 2) ? w2 : w3;
    __nv_bfloat16* dhi = g_wthi + (size_t)z * EMB * EMB;
    __nv_bfloat16* dlo = g_wtlo + (size_t)z * EMB * EMB;
    const int nb = blockIdx.x * 32, kb = blockIdx.y * 32;
    const int tx = threadIdx.x, ty = threadIdx.y;   // 32 x 8
    #pragma unroll
    for (int i = 0; i < 4; i++)
        t[ty + 8 * i][tx] = W[(size_t)(kb + ty + 8 * i) * EMB + nb + tx];
    __syncthreads();
    #pragma unroll
    for (int i = 0; i < 4; i++) {
        const int row = ty + 8 * i;                 // local n
        float v = t[tx][row];                       // = W[kb+tx][nb+row]
        __nv_bfloat16 h = __float2bfloat16(v);
        dhi[(size_t)(nb + row) * EMB + kb + tx] = h;
        dlo[(size_t)(nb + row) * EMB + kb + tx] = __float2bfloat16(v - __bfloat162float(h));
    }
}

// ============================================================================
// bf16x3 GEMM via mma.sync (HMMA): C[4096,1024] = A @ W
// block 128x128, 8 warps (4x2), warp tile 32x64, k-chunk 32, double-buffered.
// mode 0/1/2: A = x(hi/lo), W = Wq/Wk/Wv^T, scatter into g_q/g_k/g_v.
// mode 3:     A = ctx(hi/lo), W = Wo^T, add bias, write outp.
// ============================================================================
#define KC 32
#define KROWB 80                         // padded row stride in bytes (40 bf16)
#define TILE_BYTES (128 * KROWB)         // 10240
#define STAGE_BYTES (4 * TILE_BYTES)     // Ahi, Alo, Bhi, Blo = 40960
#define GEMM_SMEM (2 * STAGE_BYTES)      // 81920
#define NCHUNK (EMB / KC)                // 32

__global__ __launch_bounds__(256) void gemm_mma_kernel(
    const float* __restrict__ bias, float* __restrict__ outp, int mode_base)
{
    extern __shared__ char sb[];
    const uint32_t sbase = smem_u32(sb);
    const int tid = threadIdx.x;
    const int lane = tid & 31, wid = tid >> 5;
    const int wm = wid & 3;       // m: wm*32
    const int wn = wid >> 2;      // n: wn*64

    const int mode = mode_base + blockIdx.z;
    const __nv_bfloat16* ah = (mode == 3) ? g_chi : g_xhi;
    const __nv_bfloat16* al = (mode == 3) ? g_clo : g_xlo;
    const __nv_bfloat16* bh = g_wthi + (size_t)mode * EMB * EMB;
    const __nv_bfloat16* bl = g_wtlo + (size_t)mode * EMB * EMB;

    const int n0 = blockIdx.x * 128;
    const int m0 = blockIdx.y * 128;

    float acc[2][8][4];
    #pragma unroll
    for (int i = 0; i < 2; i++)
        #pragma unroll
        for (int j = 0; j < 8; j++)
            #pragma unroll
            for (int r = 0; r < 4; r++) acc[i][j][r] = 0.f;

    // ---- stage issue: 512 16B segments per tile, 2 per thread per tile ----
    // seg s: row = s>>2, cseg = s&3 (16B = 8 bf16 columns)
#define ISSUE_STAGE(STG, KBASE) do {                                           \
        const uint32_t st_ = sbase + (STG) * STAGE_BYTES;                      \
        _Pragma("unroll")                                                      \
        for (int t_ = 0; t_ < 2; t_++) {                                       \
            const int s_ = tid + t_ * 256;                                     \
            const int row_ = s_ >> 2, cs_ = s_ & 3;                            \
            const uint32_t so_ = row_ * KROWB + cs_ * 16;                      \
            const size_t ga_ = (size_t)(m0 + row_) * EMB + (KBASE) + cs_ * 8;  \
            const size_t gb_ = (size_t)(n0 + row_) * EMB + (KBASE) + cs_ * 8;  \
            cpa16(st_ + 0 * TILE_BYTES + so_, ah + ga_);                       \
            cpa16(st_ + 1 * TILE_BYTES + so_, al + ga_);                       \
            cpa16(st_ + 2 * TILE_BYTES + so_, bh + gb_);                       \
            cpa16(st_ + 3 * TILE_BYTES + so_, bl + gb_);                       \
        }                                                                      \
    } while (0)

    ISSUE_STAGE(0, 0);
    CPA_COMMIT();

    // fragment base offsets (bytes within a tile)
    const uint32_t a_row_off = (uint32_t)(wm * 32 + (lane & 15)) * KROWB
                             + ((lane & 16) ? 16u : 0u);              // k-half
    const uint32_t b_row_off = (uint32_t)(wn * 64 + ((lane & 16) ? 8 : 0) + (lane & 7)) * KROWB
                             + ((lane & 8) ? 16u : 0u);               // k-half

    #pragma unroll 1
    for (int c = 0; c < NCHUNK; c++) {
        if (c + 1 < NCHUNK) {
            ISSUE_STAGE((c + 1) & 1, (c + 1) * KC);
            CPA_COMMIT();
            asm volatile("cp.async.wait_group 1;" ::: "memory");
        } else {
            asm volatile("cp.async.wait_group 0;" ::: "memory");
        }
        __syncthreads();

        const uint32_t st = sbase + (c & 1) * STAGE_BYTES;
        #pragma unroll
        for (int knum = 0; knum < 2; knum++) {
            const uint32_t kb = knum * 32;    // 16 bf16 = 32 bytes
            // A fragments (hi, lo) for 2 m-subtiles
            uint32_t ahf[2][4], alf[2][4];
            #pragma unroll
            for (int mt = 0; mt < 2; mt++) {
                const uint32_t ao = st + a_row_off + (uint32_t)(mt * 16) * KROWB + kb;
                LDSM4(ahf[mt][0], ahf[mt][1], ahf[mt][2], ahf[mt][3], ao);
                LDSM4(alf[mt][0], alf[mt][1], alf[mt][2], alf[mt][3], ao + TILE_BYTES);
            }
            // B fragments: 4 pairs of n8-tiles
            #pragma unroll
            for (int npp = 0; npp < 4; npp++) {
                const uint32_t bo = st + 2 * TILE_BYTES + b_row_off
                                  + (uint32_t)(npp * 16) * KROWB + kb;
                uint32_t bh0, bh1, bh2, bh3, bl0, bl1, bl2, bl3;
                LDSM4(bh0, bh1, bh2, bh3, bo);
                LDSM4(bl0, bl1, bl2, bl3, bo + TILE_BYTES);
                #pragma unroll
                for (int mt = 0; mt < 2; mt++) {
                    MMA16816(acc[mt][2 * npp],     ahf[mt][0], ahf[mt][1], ahf[mt][2], ahf[mt][3], bh0, bh1);
                    MMA16816(acc[mt][2 * npp],     ahf[mt][0], ahf[mt][1], ahf[mt][2], ahf[mt][3], bl0, bl1);
                    MMA16816(acc[mt][2 * npp],     alf[mt][0], alf[mt][1], alf[mt][2], alf[mt][3], bh0, bh1);
                    MMA16816(acc[mt][2 * npp + 1], ahf[mt][0], ahf[mt][1], ahf[mt][2], ahf[mt][3], bh2, bh3);
                    MMA16816(acc[mt][2 * npp + 1], ahf[mt][0], ahf[mt][1], ahf[mt][2], ahf[mt][3], bl2, bl3);
                    MMA16816(acc[mt][2 * npp + 1], alf[mt][0], alf[mt][1], alf[mt][2], alf[mt][3], bh2, bh3);
                }
            }
        }
        __syncthreads();
    }

    // ---- epilogue ----
    #pragma unroll
    for (int mt = 0; mt < 2; mt++) {
        #pragma unroll
        for (int np = 0; np < 8; np++) {
            const int row = m0 + wm * 32 + mt * 16 + (lane >> 2);
            const int col = n0 + wn * 64 + np * 8 + (lane & 3) * 2;
            if (mode < 3) {
                float* dst = (mode == 0) ? g_q : (mode == 1) ? g_k : g_v;
                const int h = col >> 6, d = col & 63;
                #pragma unroll
                for (int rh = 0; rh < 2; rh++) {
                    const int r = row + rh * 8;
                    const int bb = r >> 11, ss = r & 2047;
                    float2* p = (float2*)&dst[((size_t)((bb * NH + h) * SEQ) + ss) * HD + d];
                    *p = make_float2(acc[mt][np][2 * rh], acc[mt][np][2 * rh + 1]);
                }
            } else {
                const float2 bv = *(const float2*)(bias + col);
                #pragma unroll
                for (int rh = 0; rh < 2; rh++) {
                    const int r = row + rh * 8;
                    float2* p = (float2*)&outp[(size_t)r * EMB + col];
                    *p = make_float2(acc[mt][np][2 * rh] + bv.x,
                                     acc[mt][np][2 * rh + 1] + bv.y);
                }
            }
        }
    }
#undef ISSUE_STAGE
}

// ============================================================================
// Causal flash attention, fp32; epilogue writes bf16 hi/lo ctx.
// ============================================================================
#define FS 64
#define FSTR 68
#define FLASH_SMEM (4 * FS * FSTR * (int)sizeof(float))

__global__ __launch_bounds__(128) void flash_kernel()
{
    extern __shared__ float smf[];
    float* Qs = smf;
    float* Ks = Qs + FS * FSTR;
    float* Vs = Ks + FS * FSTR;
    float* Ps = Vs + FS * FSTR;

    const int qt = blockIdx.x;
    const int h  = blockIdx.y;
    const int b  = blockIdx.z;
    const int q0 = qt * FS;

    const float* Qg = g_q + (size_t)((b * NH + h) * SEQ) * HD;
    const float* Kg = g_k + (size_t)((b * NH + h) * SEQ) * HD;
    const float* Vg = g_v + (size_t)((b * NH + h) * SEQ) * HD;

    const int tid = threadIdx.x;
    const int tx = tid & 7;
    const int ty = tid >> 3;

    {
        const int row = tid >> 4;
        const int c4  = (tid & 15) * 4;
        #pragma unroll
        for (int p = 0; p < 8; p++)
            *(float4*)&Qs[(row + p * 8) * FSTR + c4] =
                *(const float4*)(Qg + (size_t)(q0 + row + p * 8) * HD + c4);
    }

    float mrow[4], lrow[4], o[4][8];
    #pragma unroll
    for (int i = 0; i < 4; i++) {
        mrow[i] = -3.0e38f; lrow[i] = 0.f;
        #pragma unroll
        for (int c = 0; c < 8; c++) o[i][c] = 0.f;
    }

    const int ntiles = qt + 1;
    for (int jt = 0; jt < ntiles; jt++) {
        const int j0 = jt * FS;
        {
            const int row = tid >> 4;
            const int c4  = (tid & 15) * 4;
            #pragma unroll
            for (int p = 0; p < 8; p++) {
                *(float4*)&Ks[(row + p * 8) * FSTR + c4] =
                    *(const float4*)(Kg + (size_t)(j0 + row + p * 8) * HD + c4);
                *(float4*)&Vs[(row + p * 8) * FSTR + c4] =
                    *(const float4*)(Vg + (size_t)(j0 + row + p * 8) * HD + c4);
            }
        }
        __syncthreads();

        float s[4][8];
        #pragma unroll
        for (int i = 0; i < 4; i++)
            #pragma unroll
            for (int j = 0; j < 8; j++) s[i][j] = 0.f;

        #pragma unroll 4
        for (int d = 0; d < HD; d++) {
            float qv[4], kv[8];
            #pragma unroll
            for (int i = 0; i < 4; i++) qv[i] = Qs[(ty * 4 + i) * FSTR + d];
            #pragma unroll
            for (int j = 0; j < 8; j++) kv[j] = Ks[(tx + 8 * j) * FSTR + d];
            #pragma unroll
            for (int i = 0; i < 4; i++)
                #pragma unroll
                for (int j = 0; j < 8; j++)
                    s[i][j] = fmaf(qv[i], kv[j], s[i][j]);
        }

        const float scale = 0.125f;
        const bool diag = (jt == qt);
        #pragma unroll
        for (int i = 0; i < 4; i++)
            #pragma unroll
            for (int j = 0; j < 8; j++) {
                float v = s[i][j] * scale;
                if (diag && (j0 + tx + 8 * j) > (q0 + ty * 4 + i)) v = -3.0e38f;
                s[i][j] = v;
            }

        #pragma unroll
        for (int i = 0; i < 4; i++) {
            float mx = s[i][0];
            #pragma unroll
            for (int j = 1; j < 8; j++) mx = fmaxf(mx, s[i][j]);
            mx = fmaxf(mx, __shfl_xor_sync(0xffffffffu, mx, 1));
            mx = fmaxf(mx, __shfl_xor_sync(0xffffffffu, mx, 2));
            mx = fmaxf(mx, __shfl_xor_sync(0xffffffffu, mx, 4));
            const float mnew = fmaxf(mrow[i], mx);
            const float alpha = __expf(mrow[i] - mnew);
            const int r = ty * 4 + i;
            float rs = 0.f;
            #pragma unroll
            for (int j = 0; j < 8; j++) {
                const float p = __expf(s[i][j] - mnew);
                Ps[r * FSTR + tx + 8 * j] = p;
                rs += p;
            }
            rs += __shfl_xor_sync(0xffffffffu, rs, 1);
            rs += __shfl_xor_sync(0xffffffffu, rs, 2);
            rs += __shfl_xor_sync(0xffffffffu, rs, 4);
            lrow[i] = lrow[i] * alpha + rs;
            mrow[i] = mnew;
            #pragma unroll
            for (int c = 0; c < 8; c++) o[i][c] *= alpha;
        }
        __syncwarp();

        #pragma unroll 4
        for (int jj = 0; jj < FS; jj++) {
            float pv[4], vv[8];
            #pragma unroll
            for (int i = 0; i < 4; i++) pv[i] = Ps[(ty * 4 + i) * FSTR + jj];
            #pragma unroll
            for (int c = 0; c < 8; c++) vv[c] = Vs[jj * FSTR + tx + 8 * c];
            #pragma unroll
            for (int i = 0; i < 4; i++)
                #pragma unroll
                for (int c = 0; c < 8; c++)
                    o[i][c] = fmaf(pv[i], vv[c], o[i][c]);
        }
        __syncthreads();
    }

    // epilogue: ctx -> bf16 hi/lo split for the tensor-core O-projection
    #pragma unroll
    for (int i = 0; i < 4; i++) {
        const int r = q0 + ty * 4 + i;
        const float inv = 1.f / lrow[i];
        const size_t rowoff = (size_t)(b * SEQ + r) * EMB + h * HD;
        #pragma unroll
        for (int c = 0; c < 8; c++) {
            const float v = o[i][c] * inv;
            const __nv_bfloat16 hi = __float2bfloat16(v);
            g_chi[rowoff + tx + 8 * c] = hi;
            g_clo[rowoff + tx + 8 * c] = __float2bfloat16(v - __bfloat162float(hi));
        }
    }
}

// ============================================================================
// launch
// ============================================================================
extern "C" void kernel_launch(void* const* d_in, const int* in_sizes, int n_in,
                              void* d_out, int out_size)
{
    (void)in_sizes; (void)n_in; (void)out_size;
    const float* x  = (const float*)d_in[0];
    const float* wq = (const float*)d_in[1];
    const float* wk = (const float*)d_in[2];
    const float* wv = (const float*)d_in[3];
    const float* wo = (const float*)d_in[4];
    const float* bo = (const float*)d_in[5];
    float* out = (float*)d_out;

    cudaFuncSetAttribute(flash_kernel,
                         cudaFuncAttributeMaxDynamicSharedMemorySize, FLASH_SMEM);
    cudaFuncSetAttribute(gemm_mma_kernel,
                         cudaFuncAttributeMaxDynamicSharedMemorySize, GEMM_SMEM);

    // 0) split inputs to bf16 hi/lo
    conv_x_kernel<<<MROWS * EMB / (256 * 4), 256>>>(x);
    conv_w_kernel<<<dim3(EMB / 32, EMB / 32, 4), dim3(32, 8)>>>(wq, wk, wv, wo);

    // 1) QKV projections (HMMA, bf16x3) with split-head scatter
    gemm_mma_kernel<<<dim3(EMB / 128, MROWS / 128, 3), 256, GEMM_SMEM>>>(nullptr, nullptr, 0);

    // 2) causal flash attention (fp32), writes ctx as bf16 hi/lo
    flash_kernel<<<dim3(SEQ / FS, NH, BATCH), 128, FLASH_SMEM>>>();

    // 3) output projection + bias (HMMA, bf16x3)
    gemm_mma_kernel<<<dim3(EMB / 128, MROWS / 128, 1), 256, GEMM_SMEM>>>(bo, out, 3);
}

// round 4
// speedup vs baseline: 2.5880x; 1.7765x over previous
#include <cuda_runtime.h>
#include <cuda_bf16.h>
#include <stdint.h>

#define BATCH 2
#define SEQ 2048
#define EMB 1024
#define NH 16
#define HD 64
#define MROWS (BATCH * SEQ)   // 4096

// ---------------- scratch (static device allocation, allowed) ----------------
// bf16 hi/lo split operands
__device__ __nv_bfloat16 g_xhi[MROWS * EMB];
__device__ __nv_bfloat16 g_xlo[MROWS * EMB];
__device__ __nv_bfloat16 g_chi[MROWS * EMB];     // ctx (written by flash epilogue)
__device__ __nv_bfloat16 g_clo[MROWS * EMB];
__device__ __nv_bfloat16 g_wthi[4 * EMB * EMB];  // W^T [n][k], order q,k,v,o
__device__ __nv_bfloat16 g_wtlo[4 * EMB * EMB];
// attention operands (hi/lo). q,k: [b,h,s,d]; v: transposed [b,h,d,s]
__device__ __nv_bfloat16 g_qhi[BATCH * NH * SEQ * HD];
__device__ __nv_bfloat16 g_qlo[BATCH * NH * SEQ * HD];
__device__ __nv_bfloat16 g_khi[BATCH * NH * SEQ * HD];
__device__ __nv_bfloat16 g_klo[BATCH * NH * SEQ * HD];
__device__ __nv_bfloat16 g_vthi[BATCH * NH * HD * SEQ];
__device__ __nv_bfloat16 g_vtlo[BATCH * NH * HD * SEQ];

// ============================================================================
// helpers
// ============================================================================
__device__ __forceinline__ uint32_t smem_u32(const void* p) {
    uint32_t a;
    asm("{ .reg .u64 t; cvta.to.shared.u64 t, %1; cvt.u32.u64 %0, t; }" : "=r"(a) : "l"(p));
    return a;
}
__device__ __forceinline__ void cpa16(uint32_t dst, const void* src) {
    asm volatile("cp.async.cg.shared.global [%0], [%1], 16;" :: "r"(dst), "l"(src));
}
#define CPA_COMMIT() asm volatile("cp.async.commit_group;" ::: "memory")

#define LDSM4(r0, r1, r2, r3, a) \
    asm volatile("ldmatrix.sync.aligned.m8n8.x4.shared.b16 {%0,%1,%2,%3}, [%4];" \
        : "=r"(r0), "=r"(r1), "=r"(r2), "=r"(r3) : "r"(a))

#define MMA16816(c, a0, a1, a2, a3, b0, b1) \
    asm volatile("mma.sync.aligned.m16n8k16.row.col.f32.bf16.bf16.f32 " \
        "{%0,%1,%2,%3}, {%4,%5,%6,%7}, {%8,%9}, {%0,%1,%2,%3};" \
        : "+f"((c)[0]), "+f"((c)[1]), "+f"((c)[2]), "+f"((c)[3]) \
        : "r"(a0), "r"(a1), "r"(a2), "r"(a3), "r"(b0), "r"(b1))

__device__ __forceinline__ uint32_t pack_bf2(float x, float y) {
    __nv_bfloat162 t;
    t.x = __float2bfloat16(x); t.y = __float2bfloat16(y);
    return *(uint32_t*)&t;
}
__device__ __forceinline__ void split_store(float v0, float v1,
                                            __nv_bfloat16* dhi, __nv_bfloat16* dlo) {
    __nv_bfloat162 hp, lp;
    hp.x = __float2bfloat16(v0); hp.y = __float2bfloat16(v1);
    lp.x = __float2bfloat16(v0 - __bfloat162float(hp.x));
    lp.y = __float2bfloat16(v1 - __bfloat162float(hp.y));
    *(__nv_bfloat162*)dhi = hp;
    *(__nv_bfloat162*)dlo = lp;
}

// ============================================================================
// conversion kernels
// ============================================================================
__global__ void conv_x_kernel(const float* __restrict__ x) {
    int i = (blockIdx.x * 256 + threadIdx.x) * 4;
    float4 v = *(const float4*)(x + i);
    split_store(v.x, v.y, g_xhi + i, g_xlo + i);
    split_store(v.z, v.w, g_xhi + i + 2, g_xlo + i + 2);
}

// transpose + split W[k][n] -> Wt[n][k] (hi, lo)
__global__ void conv_w_kernel(const float* __restrict__ w0, const float* __restrict__ w1,
                              const float* __restrict__ w2, const float* __restrict__ w3) {
    __shared__ float t[32][33];
    const int z = blockIdx.z;
    const float* W = (z == 0) ? w0 : (z == 1) ? w1 : (z == 2) ? w2 : w3;
    __nv_bfloat16* dhi = g_wthi + (size_t)z * EMB * EMB;
    __nv_bfloat16* dlo = g_wtlo + (size_t)z * EMB * EMB;
    const int nb = blockIdx.x * 32, kb = blockIdx.y * 32;
    const int tx = threadIdx.x, ty = threadIdx.y;   // 32 x 8
    #pragma unroll
    for (int i = 0; i < 4; i++)
        t[ty + 8 * i][tx] = W[(size_t)(kb + ty + 8 * i) * EMB + nb + tx];
    __syncthreads();
    #pragma unroll
    for (int i = 0; i < 4; i++) {
        const int row = ty + 8 * i;                 // local n
        float v = t[tx][row];                       // = W[kb+tx][nb+row]
        __nv_bfloat16 h = __float2bfloat16(v);
        dhi[(size_t)(nb + row) * EMB + kb + tx] = h;
        dlo[(size_t)(nb + row) * EMB + kb + tx] = __float2bfloat16(v - __bfloat162float(h));
    }
}

// ============================================================================
// bf16x3 GEMM via mma.sync: C[M,N] = A @ B^T (both operands [rows][k] bf16 hi/lo)
// block 128x128, 8 warps (4x2), warp tile 32x64, k-chunk 32, double-buffered.
// mode 0: A=x, B=Wq^T  -> q hi/lo [b,h,s,d], scaled 0.125
// mode 1: A=x, B=Wk^T  -> k hi/lo [b,h,s,d]
// mode 2: A=Wv^T, B=x  -> C = V^T -> vt hi/lo [b,h,d,s]   (grid axes swapped)
// mode 3: A=ctx, B=Wo^T -> fp32 out + bias
// ============================================================================
#define KC 32
#define KROWB 80                         // padded row stride in bytes (40 bf16)
#define TILE_BYTES (128 * KROWB)         // 10240
#define STAGE_BYTES (4 * TILE_BYTES)     // Ahi, Alo, Bhi, Blo = 40960
#define GEMM_SMEM (2 * STAGE_BYTES)      // 81920
#define NCHUNK (EMB / KC)                // 32

__global__ __launch_bounds__(256) void gemm_mma_kernel(
    const float* __restrict__ bias, float* __restrict__ outp, int mode_base)
{
    extern __shared__ char sb[];
    const uint32_t sbase = smem_u32(sb);
    const int tid = threadIdx.x;
    const int lane = tid & 31, wid = tid >> 5;
    const int wm = wid & 3;       // m: wm*32
    const int wn = wid >> 2;      // n: wn*64

    const int mode = mode_base + blockIdx.z;

    const __nv_bfloat16 *ah, *al, *bh, *bl;
    int m0, n0;
    if (mode == 2) {
        ah = g_wthi + 2 * (size_t)EMB * EMB; al = g_wtlo + 2 * (size_t)EMB * EMB;
        bh = g_xhi; bl = g_xlo;
        m0 = blockIdx.x * 128; n0 = blockIdx.y * 128;
    } else {
        ah = (mode == 3) ? g_chi : g_xhi;
        al = (mode == 3) ? g_clo : g_xlo;
        bh = g_wthi + (size_t)mode * EMB * EMB;
        bl = g_wtlo + (size_t)mode * EMB * EMB;
        n0 = blockIdx.x * 128; m0 = blockIdx.y * 128;
    }

    float acc[2][8][4];
    #pragma unroll
    for (int i = 0; i < 2; i++)
        #pragma unroll
        for (int j = 0; j < 8; j++)
            #pragma unroll
            for (int r = 0; r < 4; r++) acc[i][j][r] = 0.f;

#define ISSUE_STAGE(STG, KBASE) do {                                           \
        const uint32_t st_ = sbase + (STG) * STAGE_BYTES;                      \
        _Pragma("unroll")                                                      \
        for (int t_ = 0; t_ < 2; t_++) {                                       \
            const int s_ = tid + t_ * 256;                                     \
            const int row_ = s_ >> 2, cs_ = s_ & 3;                            \
            const uint32_t so_ = row_ * KROWB + cs_ * 16;                      \
            const size_t ga_ = (size_t)(m0 + row_) * EMB + (KBASE) + cs_ * 8;  \
            const size_t gb_ = (size_t)(n0 + row_) * EMB + (KBASE) + cs_ * 8;  \
            cpa16(st_ + 0 * TILE_BYTES + so_, ah + ga_);                       \
            cpa16(st_ + 1 * TILE_BYTES + so_, al + ga_);                       \
            cpa16(st_ + 2 * TILE_BYTES + so_, bh + gb_);                       \
            cpa16(st_ + 3 * TILE_BYTES + so_, bl + gb_);                       \
        }                                                                      \
    } while (0)

    ISSUE_STAGE(0, 0);
    CPA_COMMIT();

    const uint32_t a_row_off = (uint32_t)(wm * 32 + (lane & 15)) * KROWB
                             + ((lane & 16) ? 16u : 0u);
    const uint32_t b_row_off = (uint32_t)(wn * 64 + ((lane & 16) ? 8 : 0) + (lane & 7)) * KROWB
                             + ((lane & 8) ? 16u : 0u);

    #pragma unroll 1
    for (int c = 0; c < NCHUNK; c++) {
        if (c + 1 < NCHUNK) {
            ISSUE_STAGE((c + 1) & 1, (c + 1) * KC);
            CPA_COMMIT();
            asm volatile("cp.async.wait_group 1;" ::: "memory");
        } else {
            asm volatile("cp.async.wait_group 0;" ::: "memory");
        }
        __syncthreads();

        const uint32_t st = sbase + (c & 1) * STAGE_BYTES;
        #pragma unroll
        for (int knum = 0; knum < 2; knum++) {
            const uint32_t kb = knum * 32;
            uint32_t ahf[2][4], alf[2][4];
            #pragma unroll
            for (int mt = 0; mt < 2; mt++) {
                const uint32_t ao = st + a_row_off + (uint32_t)(mt * 16) * KROWB + kb;
                LDSM4(ahf[mt][0], ahf[mt][1], ahf[mt][2], ahf[mt][3], ao);
                LDSM4(alf[mt][0], alf[mt][1], alf[mt][2], alf[mt][3], ao + TILE_BYTES);
            }
            #pragma unroll
            for (int npp = 0; npp < 4; npp++) {
                const uint32_t bo = st + 2 * TILE_BYTES + b_row_off
                                  + (uint32_t)(npp * 16) * KROWB + kb;
                uint32_t bh0, bh1, bh2, bh3, bl0, bl1, bl2, bl3;
                LDSM4(bh0, bh1, bh2, bh3, bo);
                LDSM4(bl0, bl1, bl2, bl3, bo + TILE_BYTES);
                #pragma unroll
                for (int mt = 0; mt < 2; mt++) {
                    MMA16816(acc[mt][2 * npp],     ahf[mt][0], ahf[mt][1], ahf[mt][2], ahf[mt][3], bh0, bh1);
                    MMA16816(acc[mt][2 * npp],     ahf[mt][0], ahf[mt][1], ahf[mt][2], ahf[mt][3], bl0, bl1);
                    MMA16816(acc[mt][2 * npp],     alf[mt][0], alf[mt][1], alf[mt][2], alf[mt][3], bh0, bh1);
                    MMA16816(acc[mt][2 * npp + 1], ahf[mt][0], ahf[mt][1], ahf[mt][2], ahf[mt][3], bh2, bh3);
                    MMA16816(acc[mt][2 * npp + 1], ahf[mt][0], ahf[mt][1], ahf[mt][2], ahf[mt][3], bl2, bl3);
                    MMA16816(acc[mt][2 * npp + 1], alf[mt][0], alf[mt][1], alf[mt][2], alf[mt][3], bh2, bh3);
                }
            }
        }
        __syncthreads();
    }

    // ---- epilogue ----
    #pragma unroll
    for (int mt = 0; mt < 2; mt++) {
        #pragma unroll
        for (int np = 0; np < 8; np++) {
            const int rbase = m0 + wm * 32 + mt * 16 + (lane >> 2);
            const int col = n0 + wn * 64 + np * 8 + (lane & 3) * 2;
            #pragma unroll
            for (int rh = 0; rh < 2; rh++) {
                const int r = rbase + rh * 8;
                const float v0 = acc[mt][np][2 * rh];
                const float v1 = acc[mt][np][2 * rh + 1];
                if (mode == 0 || mode == 1) {
                    const float sc = (mode == 0) ? 0.125f : 1.0f;
                    const int bb = r >> 11, ss = r & 2047;
                    const int hh = col >> 6, dd = col & 63;
                    const size_t off = ((size_t)(bb * NH + hh) * SEQ + ss) * HD + dd;
                    __nv_bfloat16* dhi = (mode == 0) ? g_qhi : g_khi;
                    __nv_bfloat16* dlo = (mode == 0) ? g_qlo : g_klo;
                    split_store(v0 * sc, v1 * sc, dhi + off, dlo + off);
                } else if (mode == 2) {
                    const int hh = r >> 6, dd = r & 63;       // row = feature
                    const int bb = col >> 11, ss = col & 2047; // col = token
                    const size_t off = ((size_t)(bb * NH + hh) * HD + dd) * SEQ + ss;
                    split_store(v0, v1, g_vthi + off, g_vtlo + off);
                } else {
                    const float2 bv = *(const float2*)(bias + col);
                    float2* p = (float2*)&outp[(size_t)r * EMB + col];
                    *p = make_float2(v0 + bv.x, v1 + bv.y);
                }
            }
        }
    }
#undef ISSUE_STAGE
}

// ============================================================================
// Tensor-core causal flash attention (bf16x3 split), FA2 register pipeline.
// BQ=128 q-rows/block, 8 warps (m16 each), BK=64 kv per tile, double-buffered.
// ============================================================================
#define BQ 128
#define BK 64
#define SROW 144                 // bytes per smem row (128 data + 16 pad)
#define QTILE (BQ * SROW)        // 18432
#define KTILE (BK * SROW)        // 9216
#define OFF_Q 0
#define OFF_KV (2 * QTILE)
#define FSTAGE (4 * KTILE)       // Khi,Klo,Vhi,Vlo = 36864
#define FL_SMEM (2 * QTILE + 2 * FSTAGE)   // 110592

__global__ __launch_bounds__(256) void flash_tc_kernel()
{
    extern __shared__ char sb[];
    const uint32_t S = smem_u32(sb);
    const int tid = threadIdx.x, lane = tid & 31, wid = tid >> 5;

    const int qb = (SEQ / BQ - 1) - blockIdx.x;   // reversed: heavy blocks first
    const int h = blockIdx.y, b = blockIdx.z;
    const int bh = b * NH + h;
    const int q0 = qb * BQ;

    const __nv_bfloat16* Qhi = g_qhi + (size_t)bh * SEQ * HD;
    const __nv_bfloat16* Qlo = g_qlo + (size_t)bh * SEQ * HD;
    const __nv_bfloat16* Khi = g_khi + (size_t)bh * SEQ * HD;
    const __nv_bfloat16* Klo = g_klo + (size_t)bh * SEQ * HD;
    const __nv_bfloat16* Vhi = g_vthi + (size_t)bh * HD * SEQ;
    const __nv_bfloat16* Vlo = g_vtlo + (size_t)bh * HD * SEQ;

#define ISSUE_KV(STG, J0) do {                                                \
        const uint32_t SB_ = S + OFF_KV + (STG) * FSTAGE;                     \
        _Pragma("unroll")                                                     \
        for (int t_ = 0; t_ < 2; t_++) {                                      \
            const int s_ = tid + t_ * 256;                                    \
            const int row_ = s_ >> 3, sg_ = s_ & 7;                           \
            const uint32_t so_ = row_ * SROW + sg_ * 16;                      \
            cpa16(SB_ + so_,             Khi + (size_t)((J0) + row_) * HD + sg_ * 8); \
            cpa16(SB_ + KTILE + so_,     Klo + (size_t)((J0) + row_) * HD + sg_ * 8); \
            cpa16(SB_ + 2 * KTILE + so_, Vhi + (size_t)row_ * SEQ + (J0) + sg_ * 8);  \
            cpa16(SB_ + 3 * KTILE + so_, Vlo + (size_t)row_ * SEQ + (J0) + sg_ * 8);  \
        }                                                                     \
    } while (0)

    // prologue: Q tile + KV tile 0 in one group
    #pragma unroll
    for (int t = 0; t < 4; t++) {
        const int s_ = tid + t * 256;              // 0..1023
        const int row = s_ >> 3, sg = s_ & 7;
        const uint32_t so = row * SROW + sg * 16;
        cpa16(S + OFF_Q + so,         Qhi + (size_t)(q0 + row) * HD + sg * 8);
        cpa16(S + OFF_Q + QTILE + so, Qlo + (size_t)(q0 + row) * HD + sg * 8);
    }
    ISSUE_KV(0, 0);
    CPA_COMMIT();

    float m0v = -1e30f, m1v = -1e30f, l0 = 0.f, l1 = 0.f;
    float o[8][4];
    #pragma unroll
    for (int i = 0; i < 8; i++)
        #pragma unroll
        for (int j = 0; j < 4; j++) o[i][j] = 0.f;

    uint32_t qh[4][4], ql[4][4];

    const uint32_t kfrag_off = (uint32_t)(((lane & 7) + ((lane & 16) ? 8 : 0)) * SROW)
                             + ((lane & 8) ? 16u : 0u);
    const int ntiles = (q0 + BQ) / BK;

    #pragma unroll 1
    for (int jt = 0; jt < ntiles; jt++) {
        const int j0 = jt * BK;
        if (jt + 1 < ntiles) {
            ISSUE_KV((jt + 1) & 1, j0 + BK);
            CPA_COMMIT();
            asm volatile("cp.async.wait_group 1;" ::: "memory");
        } else {
            asm volatile("cp.async.wait_group 0;" ::: "memory");
        }
        __syncthreads();

        if (jt == 0) {
            const uint32_t qa = S + OFF_Q + (uint32_t)((wid * 16 + (lane & 15)) * SROW)
                              + ((lane & 16) ? 16u : 0u);
            #pragma unroll
            for (int ks = 0; ks < 4; ks++) {
                LDSM4(qh[ks][0], qh[ks][1], qh[ks][2], qh[ks][3], qa + ks * 32);
                LDSM4(ql[ks][0], ql[ks][1], ql[ks][2], ql[ks][3], qa + QTILE + ks * 32);
            }
        }

        const uint32_t SB = S + OFF_KV + (jt & 1) * FSTAGE;

        // ---- S = Q K^T (3-term split) ----
        float s[8][4];
        #pragma unroll
        for (int i = 0; i < 8; i++)
            #pragma unroll
            for (int j = 0; j < 4; j++) s[i][j] = 0.f;

        #pragma unroll
        for (int ks = 0; ks < 4; ks++) {
            #pragma unroll
            for (int g = 0; g < 4; g++) {
                const uint32_t ka = SB + kfrag_off + (uint32_t)(g * 16) * SROW + ks * 32;
                uint32_t kh0, kh1, kh2, kh3, kl0, kl1, kl2, kl3;
                LDSM4(kh0, kh1, kh2, kh3, ka);
                LDSM4(kl0, kl1, kl2, kl3, ka + KTILE);
                MMA16816(s[2 * g],     qh[ks][0], qh[ks][1], qh[ks][2], qh[ks][3], kh0, kh1);
                MMA16816(s[2 * g],     qh[ks][0], qh[ks][1], qh[ks][2], qh[ks][3], kl0, kl1);
                MMA16816(s[2 * g],     ql[ks][0], ql[ks][1], ql[ks][2], ql[ks][3], kh0, kh1);
                MMA16816(s[2 * g + 1], qh[ks][0], qh[ks][1], qh[ks][2], qh[ks][3], kh2, kh3);
                MMA16816(s[2 * g + 1], qh[ks][0], qh[ks][1], qh[ks][2], qh[ks][3], kl2, kl3);
                MMA16816(s[2 * g + 1], ql[ks][0], ql[ks][1], ql[ks][2], ql[ks][3], kh2, kh3);
            }
        }

        // ---- causal mask ----
        const int r0 = q0 + wid * 16 + (lane >> 2);
        if (j0 + BK - 1 > q0 + wid * 16) {
            #pragma unroll
            for (int nt = 0; nt < 8; nt++) {
                const int cbase = j0 + nt * 8 + (lane & 3) * 2;
                if (cbase > r0)     s[nt][0] = -1e30f;
                if (cbase + 1 > r0) s[nt][1] = -1e30f;
                if (cbase > r0 + 8)     s[nt][2] = -1e30f;
                if (cbase + 1 > r0 + 8) s[nt][3] = -1e30f;
            }
        }

        // ---- online softmax ----
        float mx0 = -1e30f, mx1 = -1e30f;
        #pragma unroll
        for (int nt = 0; nt < 8; nt++) {
            mx0 = fmaxf(mx0, fmaxf(s[nt][0], s[nt][1]));
            mx1 = fmaxf(mx1, fmaxf(s[nt][2], s[nt][3]));
        }
        mx0 = fmaxf(mx0, __shfl_xor_sync(0xffffffffu, mx0, 1));
        mx0 = fmaxf(mx0, __shfl_xor_sync(0xffffffffu, mx0, 2));
        mx1 = fmaxf(mx1, __shfl_xor_sync(0xffffffffu, mx1, 1));
        mx1 = fmaxf(mx1, __shfl_xor_sync(0xffffffffu, mx1, 2));

        const float mn0 = fmaxf(m0v, mx0);
        const float mn1 = fmaxf(m1v, mx1);
        const float al0 = __expf(m0v - mn0);
        const float al1 = __expf(m1v - mn1);

        float rs0 = 0.f, rs1 = 0.f;
        #pragma unroll
        for (int nt = 0; nt < 8; nt++) {
            s[nt][0] = __expf(s[nt][0] - mn0);
            s[nt][1] = __expf(s[nt][1] - mn0);
            s[nt][2] = __expf(s[nt][2] - mn1);
            s[nt][3] = __expf(s[nt][3] - mn1);
            rs0 += s[nt][0] + s[nt][1];
            rs1 += s[nt][2] + s[nt][3];
        }
        rs0 += __shfl_xor_sync(0xffffffffu, rs0, 1);
        rs0 += __shfl_xor_sync(0xffffffffu, rs0, 2);
        rs1 += __shfl_xor_sync(0xffffffffu, rs1, 1);
        rs1 += __shfl_xor_sync(0xffffffffu, rs1, 2);
        l0 = l0 * al0 + rs0;
        l1 = l1 * al1 + rs1;
        m0v = mn0; m1v = mn1;

        #pragma unroll
        for (int nt = 0; nt < 8; nt++) {
            o[nt][0] *= al0; o[nt][1] *= al0;
            o[nt][2] *= al1; o[nt][3] *= al1;
        }

        // ---- O += P V (3-term split) ----
        const uint32_t vbase = SB + 2 * KTILE + kfrag_off;
        #pragma unroll
        for (int ks = 0; ks < 4; ks++) {
            // pack P fragments (A operand m16k16) for kv k-step ks
            uint32_t ph[4], pl[4];
            {
                const float p00 = s[2 * ks][0],     p01 = s[2 * ks][1];
                const float p10 = s[2 * ks][2],     p11 = s[2 * ks][3];
                const float p20 = s[2 * ks + 1][0], p21 = s[2 * ks + 1][1];
                const float p30 = s[2 * ks + 1][2], p31 = s[2 * ks + 1][3];
                ph[0] = pack_bf2(p00, p01);
                ph[1] = pack_bf2(p10, p11);
                ph[2] = pack_bf2(p20, p21);
                ph[3] = pack_bf2(p30, p31);
                __nv_bfloat162 t;
                t = *(__nv_bfloat162*)&ph[0];
                pl[0] = pack_bf2(p00 - __bfloat162float(t.x), p01 - __bfloat162float(t.y));
                t = *(__nv_bfloat162*)&ph[1];
                pl[1] = pack_bf2(p10 - __bfloat162float(t.x), p11 - __bfloat162float(t.y));
                t = *(__nv_bfloat162*)&ph[2];
                pl[2] = pack_bf2(p20 - __bfloat162float(t.x), p21 - __bfloat162float(t.y));
                t = *(__nv_bfloat162*)&ph[3];
                pl[3] = pack_bf2(p30 - __bfloat162float(t.x), p31 - __bfloat162float(t.y));
            }
            #pragma unroll
            for (int dt = 0; dt < 4; dt++) {
                const uint32_t va = vbase + (uint32_t)(dt * 16) * SROW + ks * 32;
                uint32_t vh0, vh1, vh2, vh3, vl0, vl1, vl2, vl3;
                LDSM4(vh0, vh1, vh2, vh3, va);
                LDSM4(vl0, vl1, vl2, vl3, va + KTILE);
                MMA16816(o[2 * dt],     ph[0], ph[1], ph[2], ph[3], vh0, vh1);
                MMA16816(o[2 * dt],     pl[0], pl[1], pl[2], pl[3], vh0, vh1);
                MMA16816(o[2 * dt],     ph[0], ph[1], ph[2], ph[3], vl0, vl1);
                MMA16816(o[2 * dt + 1], ph[0], ph[1], ph[2], ph[3], vh2, vh3);
                MMA16816(o[2 * dt + 1], pl[0], pl[1], pl[2], pl[3], vh2, vh3);
                MMA16816(o[2 * dt + 1], ph[0], ph[1], ph[2], ph[3], vl2, vl3);
            }
        }
        __syncthreads();
    }

    // ---- epilogue: ctx bf16 hi/lo, [b, s, h*64 + d] ----
    const float inv0 = 1.f / l0;
    const float inv1 = 1.f / l1;
    const int r0 = q0 + wid * 16 + (lane >> 2);
    #pragma unroll
    for (int nt = 0; nt < 8; nt++) {
        const int d = nt * 8 + (lane & 3) * 2;
        const size_t off0 = ((size_t)(b * SEQ + r0)) * EMB + h * HD + d;
        const size_t off1 = off0 + (size_t)8 * EMB;
        split_store(o[nt][0] * inv0, o[nt][1] * inv0, g_chi + off0, g_clo + off0);
        split_store(o[nt][2] * inv1, o[nt][3] * inv1, g_chi + off1, g_clo + off1);
    }
#undef ISSUE_KV
}

// ============================================================================
// launch
// ============================================================================
extern "C" void kernel_launch(void* const* d_in, const int* in_sizes, int n_in,
                              void* d_out, int out_size)
{
    (void)in_sizes; (void)n_in; (void)out_size;
    const float* x  = (const float*)d_in[0];
    const float* wq = (const float*)d_in[1];
    const float* wk = (const float*)d_in[2];
    const float* wv = (const float*)d_in[3];
    const float* wo = (const float*)d_in[4];
    const float* bo = (const float*)d_in[5];
    float* out = (float*)d_out;

    cudaFuncSetAttribute(gemm_mma_kernel,
                         cudaFuncAttributeMaxDynamicSharedMemorySize, GEMM_SMEM);
    cudaFuncSetAttribute(flash_tc_kernel,
                         cudaFuncAttributeMaxDynamicSharedMemorySize, FL_SMEM);

    // 0) split inputs to bf16 hi/lo
    conv_x_kernel<<<MROWS * EMB / (256 * 4), 256>>>(x);
    conv_w_kernel<<<dim3(EMB / 32, EMB / 32, 4), dim3(32, 8)>>>(wq, wk, wv, wo);

    // 1) Q,K,V^T projections (HMMA bf16x3) with split-head hi/lo epilogues
    gemm_mma_kernel<<<dim3(8, 32, 3), 256, GEMM_SMEM>>>(nullptr, nullptr, 0);

    // 2) causal flash attention (tensor cores), writes ctx as bf16 hi/lo
    flash_tc_kernel<<<dim3(SEQ / BQ, NH, BATCH), 256, FL_SMEM>>>();

    // 3) output projection + bias
    gemm_mma_kernel<<<dim3(8, 32, 1), 256, GEMM_SMEM>>>(bo, out, 3);
}